// round 12
// baseline (speedup 1.0000x reference)
#include <cuda_runtime.h>
#include <math.h>

#define N_NODES_C 100000
#define N_PATHS_C 1000000
#define T_C 16
#define F_C 9

#define QSCALE 16384.0f
#define QINV   (1.0f / 16384.0f)

// Node record: 16 x int16 (32B, one L2 sector): [0..8]=Re(log X_f)*2^14,
// [9..15]=Im(log X_f)*2^14 for f=1..7. 32B-aligned -> never straddles a line.
__device__ int2 g_tab[N_NODES_C * 4];     // record n = g_tab[4n .. 4n+3]
__device__ int g_seg_start[N_PATHS_C + 1];

// ---------------------------------------------------------------------------
// Compile-time twiddles: cos(pi*k/8), sin(pi*k/8). Folds to FFMA immediates.
// ---------------------------------------------------------------------------
__device__ __forceinline__ float COSPI16(int k) {
    switch (((k % 16) + 16) & 15) {
        case 0:  return  1.0f;
        case 1:  return  0.9238795325112867f;
        case 2:  return  0.7071067811865476f;
        case 3:  return  0.3826834323650898f;
        case 4:  return  0.0f;
        case 5:  return -0.3826834323650898f;
        case 6:  return -0.7071067811865476f;
        case 7:  return -0.9238795325112867f;
        case 8:  return -1.0f;
        case 9:  return -0.9238795325112867f;
        case 10: return -0.7071067811865476f;
        case 11: return -0.3826834323650898f;
        case 12: return  0.0f;
        case 13: return  0.3826834323650898f;
        case 14: return  0.7071067811865476f;
        default: return  0.9238795325112867f;
    }
}
__device__ __forceinline__ float SINPI16(int k) { return COSPI16(k - 4); }

__device__ __forceinline__ int q16(float v) {
    int x = __float2int_rn(v * QSCALE);
    x = max(-32768, min(32767, x));
    return x;
}
__device__ __forceinline__ int pack16(int a, int b) {
    return (a & 0xFFFF) | (b << 16);
}

// ---------------------------------------------------------------------------
// Kernel A: per-node log-spectrum via geometric closed form:
//   X_f = inv_k*(1-r^16) / (1 - r*e^{-i*pi*f/8}),  r = exp(-1/k)
// Quantized to int16*2^14, packed 32B per node.
// ---------------------------------------------------------------------------
__global__ __launch_bounds__(256)
void node_irf_kernel(const float* __restrict__ params, int n_nodes) {
    int n = blockIdx.x * blockDim.x + threadIdx.x;
    if (n >= n_nodes) return;

    float k = params[n] + 0.5f;
    float inv_k = 1.0f / k;
    float r = expf(-inv_k);
    float r2 = r * r, r4 = r2 * r2, r8 = r4 * r4, r16 = r8 * r8;
    float C = logf(inv_k * (1.0f - r16));

    int q[16];
    q[0] = q16(C - logf(1.0f - r));       // f=0
    q[8] = q16(C - logf(1.0f + r));       // f=8 (Nyquist)
#pragma unroll
    for (int f = 1; f <= 7; f++) {
        float dre = 1.0f - r * COSPI16(f);
        float dim = r * SINPI16(f);
        q[f]     = q16(C - 0.5f * logf(dre * dre + dim * dim));
        q[8 + f] = q16(-atan2f(dim, dre));
    }

    int4* dst = reinterpret_cast<int4*>(&g_tab[n * 4]);
    dst[0] = make_int4(pack16(q[0],  q[1]),  pack16(q[2],  q[3]),
                       pack16(q[4],  q[5]),  pack16(q[6],  q[7]));
    dst[1] = make_int4(pack16(q[8],  q[9]),  pack16(q[10], q[11]),
                       pack16(q[12], q[13]), pack16(q[14], q[15]));
}

// ---------------------------------------------------------------------------
// Kernel B: segment starts from sorted path_idxs (deterministic).
// ---------------------------------------------------------------------------
__global__ __launch_bounds__(256)
void seg_start_kernel(const int* __restrict__ path_idxs, int e_total, int n_paths) {
    int i = blockIdx.x * blockDim.x + threadIdx.x;
    if (i >= e_total) return;
    int cur = path_idxs[i];
    int prev = __shfl_up_sync(0xffffffffu, cur, 1);
    if ((threadIdx.x & 31) == 0) {
        prev = (i == 0) ? -1 : __ldg(path_idxs + i - 1);
    }
    for (int q = prev + 1; q <= cur; q++) g_seg_start[q] = i;
    if (i == e_total - 1) {
        for (int q = cur + 1; q <= n_paths; q++) g_seg_start[q] = e_total;
    }
}

// ---------------------------------------------------------------------------
// Kernel C: Phase 1 — fused per-quad work list. Each quad (4 lanes) streams
// through its 4 paths (m = 0..3, path = base + m*64 + g) continuously; the
// warp-level divergence penalty is max over quads of TOTAL quad work instead
// of a per-sub-phase max (expected warp chunk-iters ~10 -> ~7.5). Lane j
// loads int2 slot j of the 32B record (one sector, one wavefront/record).
// Exact int32 accumulation -> deterministic. Phase 2 — one thread per path:
// dequant, complex exp, analytic 16-pt irfft, relu, flip, normalize.
// ---------------------------------------------------------------------------
#define AGG_TPB 256
#define PATHS_PER_BLK 256
#define CHUNK 8

__global__ __launch_bounds__(AGG_TPB, 4)
void agg_kernel(const int* __restrict__ path_nodes,
                float* __restrict__ out, int n_paths) {
    __shared__ int s_acc[PATHS_PER_BLK][17];   // stride 17: conflict-free

    int tid = threadIdx.x;
    int block_base = blockIdx.x * PATHS_PER_BLK;
    int j = tid & 3;     // int2 slot within 32B record
    int g = tid >> 2;    // quad id 0..63

    const int2* tab = g_tab;

    // ---- Phase 1: fused gather over this quad's 4 paths ----
    int m = 0;                 // which of the quad's 4 paths
    int a0 = 0, a1 = 0, a2 = 0, a3 = 0;
    int s = 0, e = 0, i = 0;
    {
        int p = block_base + g;
        if (p < n_paths) { s = g_seg_start[p]; e = g_seg_start[p + 1]; }
        i = s;
    }

    while (true) {
        // Advance past completed (or empty) paths; store their accumulators.
        while (m < 4 && i >= e) {
            int lp = m * 64 + g;
            s_acc[lp][j * 4 + 0] = a0;
            s_acc[lp][j * 4 + 1] = a1;
            s_acc[lp][j * 4 + 2] = a2;
            s_acc[lp][j * 4 + 3] = a3;
            a0 = a1 = a2 = a3 = 0;
            m++;
            if (m < 4) {
                int p = block_base + m * 64 + g;
                if (p < n_paths) { s = g_seg_start[p]; e = g_seg_start[p + 1]; }
                else             { s = 0; e = 0; }
                i = s;
            }
        }
        if (!__any_sync(0xffffffffu, m < 4)) break;

        bool act = (m < 4);
        int nn[CHUNK];
#pragma unroll
        for (int kk = 0; kk < CHUNK; kk++) {
            nn[kk] = (act && i + kk < e) ? __ldg(path_nodes + i + kk) : -1;
        }
        int2 vv[CHUNK];
#pragma unroll
        for (int kk = 0; kk < CHUNK; kk++) {
            vv[kk] = (nn[kk] >= 0) ? __ldg(tab + nn[kk] * 4 + j)
                                   : make_int2(0, 0);
        }
#pragma unroll
        for (int kk = 0; kk < CHUNK; kk++) {
            a0 += (int)(short)vv[kk].x;
            a1 += vv[kk].x >> 16;
            a2 += (int)(short)vv[kk].y;
            a3 += vv[kk].y >> 16;
        }
        i += CHUNK;
    }
    __syncthreads();

    // ---- Phase 2: one thread per path ----
    int p = block_base + tid;
    if (p >= n_paths) return;

    float acc[16];
#pragma unroll
    for (int c = 0; c < 16; c++) acc[c] = (float)s_acc[tid][c] * QINV;

    // complex exp of aggregated logs (CASCADE = 1)
    float Xr[F_C], Xi[F_C];
    Xr[0] = expf(acc[0]);  Xi[0] = 0.0f;
    Xr[8] = expf(acc[8]);  Xi[8] = 0.0f;
#pragma unroll
    for (int f = 1; f <= 7; f++) {
        float m2 = expf(acc[f]);
        float si, co;
        sincosf(acc[8 + f], &si, &co);
        Xr[f] = m2 * co;
        Xi[f] = m2 * si;
    }

    // irfft (n=16) with t <-> 16-t symmetry, constant twiddles.
    float x[T_C];
#pragma unroll
    for (int t = 0; t <= 8; t++) {
        float cs = 0.0f, ss = 0.0f;
#pragma unroll
        for (int f = 1; f <= 7; f++) {
            cs += Xr[f] * COSPI16(f * t);
            ss += Xi[f] * SINPI16(f * t);
        }
        float base = Xr[0] + ((t & 1) ? -Xr[8] : Xr[8]);
        float v1 = (base + 2.0f * (cs - ss)) * 0.0625f;
        if (t == 0) {
            x[0] = v1;
        } else if (t == 8) {
            x[8] = v1;
        } else {
            x[t] = v1;
            x[16 - t] = (base + 2.0f * (cs + ss)) * 0.0625f;
        }
    }

    // relu + sum
    float sum = 0.0f;
#pragma unroll
    for (int t = 0; t < T_C; t++) {
        x[t] = fmaxf(x[t], 0.0f);
        sum += x[t];
    }
    float inv_sum = 1.0f / sum;

    // flip + normalize, coalesced float4 stores
    float4* o4 = reinterpret_cast<float4*>(out + (size_t)p * 16);
    o4[0] = make_float4(x[15] * inv_sum, x[14] * inv_sum, x[13] * inv_sum, x[12] * inv_sum);
    o4[1] = make_float4(x[11] * inv_sum, x[10] * inv_sum, x[9]  * inv_sum, x[8]  * inv_sum);
    o4[2] = make_float4(x[7]  * inv_sum, x[6]  * inv_sum, x[5]  * inv_sum, x[4]  * inv_sum);
    o4[3] = make_float4(x[3]  * inv_sum, x[2]  * inv_sum, x[1]  * inv_sum, x[0]  * inv_sum);
}

// ---------------------------------------------------------------------------
extern "C" void kernel_launch(void* const* d_in, const int* in_sizes, int n_in,
                              void* d_out, int out_size) {
    const float* params     = (const float*)d_in[0];
    const int*   path_idxs  = (const int*)d_in[1];
    const int*   path_nodes = (const int*)d_in[2];
    float*       out        = (float*)d_out;

    int n_nodes = in_sizes[0];
    int e_total = in_sizes[1];
    int n_paths = out_size / T_C;
    if (n_nodes > N_NODES_C) n_nodes = N_NODES_C;
    if (n_paths > N_PATHS_C) n_paths = N_PATHS_C;

    node_irf_kernel<<<(n_nodes + 255) / 256, 256>>>(params, n_nodes);
    seg_start_kernel<<<(e_total + 255) / 256, 256>>>(path_idxs, e_total, n_paths);
    agg_kernel<<<(n_paths + PATHS_PER_BLK - 1) / PATHS_PER_BLK, AGG_TPB>>>(path_nodes, out, n_paths);
}

// round 13
// speedup vs baseline: 1.0187x; 1.0187x over previous
#include <cuda_runtime.h>
#include <math.h>

#define N_NODES_C 100000
#define N_PATHS_C 1000000
#define T_C 16
#define F_C 9

#define QSCALE 16384.0f
#define QINV   (1.0f / 16384.0f)

// Node record: 16 x int16 (32B, one L2 sector): [0..8]=Re(log X_f)*2^14,
// [9..15]=Im(log X_f)*2^14 for f=1..7. 32B-aligned -> never straddles a line.
__device__ int2 g_tab[N_NODES_C * 4];     // record n = g_tab[4n .. 4n+3]
__device__ int g_seg_start[N_PATHS_C + 1];

// ---------------------------------------------------------------------------
// Compile-time twiddles: cos(pi*k/8), sin(pi*k/8). Folds to FFMA immediates.
// ---------------------------------------------------------------------------
__device__ __forceinline__ float COSPI16(int k) {
    switch (((k % 16) + 16) & 15) {
        case 0:  return  1.0f;
        case 1:  return  0.9238795325112867f;
        case 2:  return  0.7071067811865476f;
        case 3:  return  0.3826834323650898f;
        case 4:  return  0.0f;
        case 5:  return -0.3826834323650898f;
        case 6:  return -0.7071067811865476f;
        case 7:  return -0.9238795325112867f;
        case 8:  return -1.0f;
        case 9:  return -0.9238795325112867f;
        case 10: return -0.7071067811865476f;
        case 11: return -0.3826834323650898f;
        case 12: return  0.0f;
        case 13: return  0.3826834323650898f;
        case 14: return  0.7071067811865476f;
        default: return  0.9238795325112867f;
    }
}
__device__ __forceinline__ float SINPI16(int k) { return COSPI16(k - 4); }

__device__ __forceinline__ int q16(float v) {
    int x = __float2int_rn(v * QSCALE);
    x = max(-32768, min(32767, x));
    return x;
}
__device__ __forceinline__ int pack16(int a, int b) {
    return (a & 0xFFFF) | (b << 16);
}

// ---------------------------------------------------------------------------
// Fused Kernel A+B: blocks [0, node_blocks) build the node table (closed-form
// log-spectrum, int16-quantized, 32B/node); remaining blocks build segment
// starts from the sorted path_idxs. Disjoint outputs, no interaction.
// ---------------------------------------------------------------------------
#define NODE_TPB 256

__global__ __launch_bounds__(NODE_TPB)
void prep_kernel(const float* __restrict__ params, int n_nodes, int node_blocks,
                 const int* __restrict__ path_idxs, int e_total, int n_paths) {
    if ((int)blockIdx.x < node_blocks) {
        int n = blockIdx.x * NODE_TPB + threadIdx.x;
        if (n >= n_nodes) return;

        float k = params[n] + 0.5f;
        float inv_k = 1.0f / k;
        float r = expf(-inv_k);
        float r2 = r * r, r4 = r2 * r2, r8 = r4 * r4, r16 = r8 * r8;
        float C = logf(inv_k * (1.0f - r16));

        int q[16];
        q[0] = q16(C - logf(1.0f - r));       // f=0
        q[8] = q16(C - logf(1.0f + r));       // f=8 (Nyquist)
#pragma unroll
        for (int f = 1; f <= 7; f++) {
            float dre = 1.0f - r * COSPI16(f);
            float dim = r * SINPI16(f);
            q[f]     = q16(C - 0.5f * logf(dre * dre + dim * dim));
            q[8 + f] = q16(-atan2f(dim, dre));
        }

        int4* dst = reinterpret_cast<int4*>(&g_tab[n * 4]);
        dst[0] = make_int4(pack16(q[0],  q[1]),  pack16(q[2],  q[3]),
                           pack16(q[4],  q[5]),  pack16(q[6],  q[7]));
        dst[1] = make_int4(pack16(q[8],  q[9]),  pack16(q[10], q[11]),
                           pack16(q[12], q[13]), pack16(q[14], q[15]));
    } else {
        int i = (blockIdx.x - node_blocks) * NODE_TPB + threadIdx.x;
        if (i >= e_total) return;
        int cur = path_idxs[i];
        int prev = __shfl_up_sync(0xffffffffu, cur, 1);
        if ((threadIdx.x & 31) == 0) {
            prev = (i == 0) ? -1 : __ldg(path_idxs + i - 1);
        }
        for (int q = prev + 1; q <= cur; q++) g_seg_start[q] = i;
        if (i == e_total - 1) {
            for (int q = cur + 1; q <= n_paths; q++) g_seg_start[q] = e_total;
        }
    }
}

// ---------------------------------------------------------------------------
// Kernel C: Phase 1 — 4 lanes per path; lane j loads int2 slot j of the 32B
// record (one sector, one wavefront/record — measured at the L1tex replay
// floor, left untouched). Exact int32 accumulation. 128 paths/block to halve
// phase-boundary straggler exposure. Phase 2 — one thread per path with fast
// intrinsics (__expf / __sincosf; |args| <= ~16, error ~1e-6 abs).
// ---------------------------------------------------------------------------
#define AGG_TPB 128
#define PATHS_PER_BLK 128
#define CHUNK 8

__global__ __launch_bounds__(AGG_TPB, 8)
void agg_kernel(const int* __restrict__ path_nodes,
                float* __restrict__ out, int n_paths) {
    __shared__ int s_acc[PATHS_PER_BLK][17];   // stride 17: conflict-free

    int tid = threadIdx.x;
    int block_base = blockIdx.x * PATHS_PER_BLK;
    int j = tid & 3;     // int2 slot within 32B record
    int g = tid >> 2;    // quad id 0..31

    const int2* tab = g_tab;

    // ---- Phase 1: gather (4 sub-phases x 32 paths) ----
#pragma unroll
    for (int sp = 0; sp < 4; sp++) {
        int lp = sp * 32 + g;
        int p = block_base + lp;
        int a0 = 0, a1 = 0, a2 = 0, a3 = 0;
        if (p < n_paths) {
            int s = g_seg_start[p];
            int e = g_seg_start[p + 1];
            for (int i = s; i < e; i += CHUNK) {
                int nn[CHUNK];
#pragma unroll
                for (int kk = 0; kk < CHUNK; kk++) {
                    nn[kk] = (i + kk < e) ? __ldg(path_nodes + i + kk) : -1;
                }
                int2 vv[CHUNK];
#pragma unroll
                for (int kk = 0; kk < CHUNK; kk++) {
                    vv[kk] = (nn[kk] >= 0) ? __ldg(tab + nn[kk] * 4 + j)
                                           : make_int2(0, 0);
                }
#pragma unroll
                for (int kk = 0; kk < CHUNK; kk++) {
                    a0 += (int)(short)vv[kk].x;
                    a1 += vv[kk].x >> 16;
                    a2 += (int)(short)vv[kk].y;
                    a3 += vv[kk].y >> 16;
                }
            }
        }
        s_acc[lp][j * 4 + 0] = a0;
        s_acc[lp][j * 4 + 1] = a1;
        s_acc[lp][j * 4 + 2] = a2;
        s_acc[lp][j * 4 + 3] = a3;
    }
    __syncthreads();

    // ---- Phase 2: one thread per path ----
    int p = block_base + tid;
    if (p >= n_paths) return;

    float acc[16];
#pragma unroll
    for (int c = 0; c < 16; c++) acc[c] = (float)s_acc[tid][c] * QINV;

    // complex exp of aggregated logs (CASCADE = 1) — fast intrinsics.
    float Xr[F_C], Xi[F_C];
    Xr[0] = __expf(acc[0]);  Xi[0] = 0.0f;
    Xr[8] = __expf(acc[8]);  Xi[8] = 0.0f;
#pragma unroll
    for (int f = 1; f <= 7; f++) {
        float m = __expf(acc[f]);
        float si, co;
        __sincosf(acc[8 + f], &si, &co);
        Xr[f] = m * co;
        Xi[f] = m * si;
    }

    // irfft (n=16) with t <-> 16-t symmetry, constant twiddles.
    float x[T_C];
#pragma unroll
    for (int t = 0; t <= 8; t++) {
        float cs = 0.0f, ss = 0.0f;
#pragma unroll
        for (int f = 1; f <= 7; f++) {
            cs += Xr[f] * COSPI16(f * t);
            ss += Xi[f] * SINPI16(f * t);
        }
        float base = Xr[0] + ((t & 1) ? -Xr[8] : Xr[8]);
        float v1 = (base + 2.0f * (cs - ss)) * 0.0625f;
        if (t == 0) {
            x[0] = v1;
        } else if (t == 8) {
            x[8] = v1;
        } else {
            x[t] = v1;
            x[16 - t] = (base + 2.0f * (cs + ss)) * 0.0625f;
        }
    }

    // relu + sum
    float sum = 0.0f;
#pragma unroll
    for (int t = 0; t < T_C; t++) {
        x[t] = fmaxf(x[t], 0.0f);
        sum += x[t];
    }
    float inv_sum = 1.0f / sum;

    // flip + normalize, coalesced float4 stores
    float4* o4 = reinterpret_cast<float4*>(out + (size_t)p * 16);
    o4[0] = make_float4(x[15] * inv_sum, x[14] * inv_sum, x[13] * inv_sum, x[12] * inv_sum);
    o4[1] = make_float4(x[11] * inv_sum, x[10] * inv_sum, x[9]  * inv_sum, x[8]  * inv_sum);
    o4[2] = make_float4(x[7]  * inv_sum, x[6]  * inv_sum, x[5]  * inv_sum, x[4]  * inv_sum);
    o4[3] = make_float4(x[3]  * inv_sum, x[2]  * inv_sum, x[1]  * inv_sum, x[0]  * inv_sum);
}

// ---------------------------------------------------------------------------
extern "C" void kernel_launch(void* const* d_in, const int* in_sizes, int n_in,
                              void* d_out, int out_size) {
    const float* params     = (const float*)d_in[0];
    const int*   path_idxs  = (const int*)d_in[1];
    const int*   path_nodes = (const int*)d_in[2];
    float*       out        = (float*)d_out;

    int n_nodes = in_sizes[0];
    int e_total = in_sizes[1];
    int n_paths = out_size / T_C;
    if (n_nodes > N_NODES_C) n_nodes = N_NODES_C;
    if (n_paths > N_PATHS_C) n_paths = N_PATHS_C;

    int node_blocks = (n_nodes + NODE_TPB - 1) / NODE_TPB;
    int seg_blocks  = (e_total + NODE_TPB - 1) / NODE_TPB;

    prep_kernel<<<node_blocks + seg_blocks, NODE_TPB>>>(
        params, n_nodes, node_blocks, path_idxs, e_total, n_paths);
    agg_kernel<<<(n_paths + PATHS_PER_BLK - 1) / PATHS_PER_BLK, AGG_TPB>>>(
        path_nodes, out, n_paths);
}